// round 8
// baseline (speedup 1.0000x reference)
#include <cuda_runtime.h>
#include <math.h>

// ---------------- problem constants ----------------
#define BATCH    8192
#define TSTEPS   99
#define DIN      32
#define DH       100
#define GRP      8           // lane-slices per row
#define JT       14          // hidden cols per slice (padded to 16 in xc)
#define RW       16
#define RU       25
#define RP       28          // padded rank (phase-1 accumulator width)
#define SLST     20          // U2 slice stride (words): conflict-free
#define U2ROW    160         // U2 smem row stride = 8*20
#define NCLS     6
#define NTHREADS 64
#define ROWS_CTA 8           // 2 warps * 4 rows
#define NGRID    (BATCH / ROWS_CTA)        // 1024
#define RT_TOTAL (BATCH * TSTEPS)          // 811008
#define XW_GRID  (RT_TOTAL / 128)          // 6336
#define XW_THREADS 256

// ---------------- device-global prepped weights + scratch ----------------
__device__ float g_Wct[DIN * 128];          // [k][col], col = g*16+jl -> j=g*14+jl
__device__ float g_U1p[112 * RP];           // [slot = jl*8+g][28]
__device__ float g_U2p[RU * U2ROW];         // [r][g*20 + c]
__device__ float g_bb [112 * 2];            // interleaved (bias_gate, bias_update), j-indexed
__device__ float g_sc [2];                  // sigmoid(zeta), sigmoid(nu)
__device__ float g_xc [(size_t)RT_TOTAL * 128];   // xc[rt][128], col = g*16+jl

// ---------------- packed f32x2 FMA + tanh.approx ----------------
__device__ __forceinline__ void fma2(float2& d, float2 a, float2 b) {
    asm("fma.rn.f32x2 %0, %1, %2, %0;"
        : "+l"(reinterpret_cast<unsigned long long&>(d))
        : "l"(reinterpret_cast<unsigned long long&>(a)),
          "l"(reinterpret_cast<unsigned long long&>(b)));
}
__device__ __forceinline__ float tanha(float x) {
    float r; asm("tanh.approx.f32 %0, %1;" : "=f"(r) : "f"(x)); return r;
}
__device__ __forceinline__ float elem4(float4 v, int e) {
    return (e == 0) ? v.x : (e == 1) ? v.y : (e == 2) ? v.z : v.w;
}

// ---------------- setup: fold / pad / transpose weights (r6 verbatim) ----------------
__global__ void setup_kernel(const float* __restrict__ W1, const float* __restrict__ W2,
                             const float* __restrict__ U1, const float* __restrict__ U2,
                             const float* __restrict__ bg, const float* __restrict__ bu,
                             const float* __restrict__ zeta, const float* __restrict__ nu) {
    int tid = blockIdx.x * blockDim.x + threadIdx.x;
    int nth = gridDim.x * blockDim.x;
    for (int idx = tid; idx < DIN * 128; idx += nth) {
        int k = idx >> 7, c = idx & 127;
        int g = c >> 4, jl = c & 15;
        int j = g * JT + jl;
        float s = 0.f;
        if (jl < JT && j < DH)
            for (int r = 0; r < RW; r++) s = fmaf(W1[k * RW + r], W2[r * DH + j], s);
        g_Wct[idx] = s;
    }
    for (int idx = tid; idx < 112 * RP; idx += nth) {
        int slot = idx / RP, r = idx % RP;
        int jl = slot >> 3, g = slot & 7;
        int j = g * JT + jl;
        g_U1p[idx] = (j < DH && r < RU) ? U1[j * RU + r] : 0.f;
    }
    for (int idx = tid; idx < RU * U2ROW; idx += nth) {
        int r = idx / U2ROW, w = idx % U2ROW;
        int g = w / SLST, c = w % SLST;
        int j = g * JT + c;
        g_U2p[idx] = (c < JT && j < DH) ? U2[r * DH + j] : 0.f;
    }
    for (int j = tid; j < 112; j += nth) {
        g_bb[2 * j]     = (j < DH) ? bg[j] : 0.f;
        g_bb[2 * j + 1] = (j < DH) ? bu[j] : 0.f;
    }
    if (tid == 0) {
        g_sc[0] = 1.f / (1.f + expf(-zeta[0]));
        g_sc[1] = 1.f / (1.f + expf(-nu[0]));
    }
}

// ---------------- xw GEMM (r6 verbatim): g_xc[rt][.] = x[rt] @ Wct ----------------
__global__ void __launch_bounds__(XW_THREADS)
xw_kernel(const float* __restrict__ x) {
    __shared__ __align__(16) float Wcs[DIN * 128];
    __shared__ __align__(16) float xts[DIN * 128];

    const int tid = threadIdx.x;
    for (int i = tid; i < DIN * 128; i += XW_THREADS) Wcs[i] = g_Wct[i];

    const float4* xsrc = (const float4*)x + (size_t)blockIdx.x * 1024;
#pragma unroll
    for (int i = 0; i < 4; i++) {
        int fidx = tid * 4 + i;
        int rt_l = fidx >> 3;
        int k4   = (fidx & 7) * 4;
        float4 v = xsrc[fidx];
        xts[(k4 + 0) * 128 + rt_l] = v.x;
        xts[(k4 + 1) * 128 + rt_l] = v.y;
        xts[(k4 + 2) * 128 + rt_l] = v.z;
        xts[(k4 + 3) * 128 + rt_l] = v.w;
    }
    __syncthreads();

    const int rtg = tid >> 3;
    const int cg  = tid & 7;

    float2 acc[4][8];
#pragma unroll
    for (int r = 0; r < 4; r++)
#pragma unroll
        for (int i = 0; i < 8; i++) acc[r][i] = make_float2(0.f, 0.f);

#pragma unroll 4
    for (int k = 0; k < DIN; k++) {
        float4 xv = *(const float4*)(xts + k * 128 + rtg * 4);
#pragma unroll
        for (int q = 0; q < 4; q++) {
            float4 wv = *(const float4*)(Wcs + k * 128 + q * 32 + cg * 4);
            float2 wl = make_float2(wv.x, wv.y);
            float2 wh = make_float2(wv.z, wv.w);
#pragma unroll
            for (int r = 0; r < 4; r++) {
                float xk = elem4(xv, r);
                float2 x2 = make_float2(xk, xk);
                fma2(acc[r][2 * q],     x2, wl);
                fma2(acc[r][2 * q + 1], x2, wh);
            }
        }
    }
#pragma unroll
    for (int r = 0; r < 4; r++) {
        size_t rti = (size_t)blockIdx.x * 128 + rtg * 4 + r;
#pragma unroll
        for (int q = 0; q < 4; q++)
            *(float4*)(g_xc + rti * 128 + q * 32 + cg * 4) =
                make_float4(acc[r][2 * q].x, acc[r][2 * q].y,
                            acc[r][2 * q + 1].x, acc[r][2 * q + 1].y);
    }
}

// ---------------- fused recurrent kernel: GRP=8, RPT=1, 12 warps/SM ----------------
__global__ void __launch_bounds__(NTHREADS, 6)
grnn_kernel(const float* __restrict__ FC, const float* __restrict__ FCb,
            float* __restrict__ out) {
    __shared__ __align__(16) float U1s[112 * RP];    // 12.5 KB
    __shared__ __align__(16) float U2s[RU * U2ROW];  // 16.0 KB

    const int tid = threadIdx.x;
    for (int i = tid; i < 112 * RP; i += NTHREADS) U1s[i] = g_U1p[i];
    for (int i = tid; i < RU * U2ROW; i += NTHREADS) U2s[i] = g_U2p[i];
    __syncthreads();

    const float sz = g_sc[0];
    const float sn = g_sc[1];

    const int lane = tid & 31;
    const int g    = lane & 7;            // slice within row
    const int rg   = lane >> 3;           // row-group within warp (0..3)
    const int row  = blockIdx.x * ROWS_CTA + (tid >> 5) * 4 + rg;

    // per-lane biases hoisted to registers: 14 (gate, update) pairs
    float2 bbv[JT];
#pragma unroll
    for (int jl = 0; jl < JT; jl++)
        bbv[jl] = *(const float2*)(g_bb + 2 * (g * JT + jl));

    const float* px = g_xc + ((size_t)row * TSTEPS) * 128 + g * 16;

    float2 H[JT / 2];
#pragma unroll
    for (int i = 0; i < JT / 2; i++) H[i] = make_float2(0.f, 0.f);

    // current xc slice held raw; converted into c at loop top
    float4 cur0 = *(const float4*)(px);
    float4 cur1 = *(const float4*)(px + 4);
    float4 cur2 = *(const float4*)(px + 8);
    float4 cur3 = *(const float4*)(px + 12);

    for (int t = 0; t < TSTEPS; t++) {
        // c-init from current xc, then prefetch next step
        float2 c[8];
        c[0] = make_float2(cur0.x, cur0.y); c[1] = make_float2(cur0.z, cur0.w);
        c[2] = make_float2(cur1.x, cur1.y); c[3] = make_float2(cur1.z, cur1.w);
        c[4] = make_float2(cur2.x, cur2.y); c[5] = make_float2(cur2.z, cur2.w);
        c[6] = make_float2(cur3.x, cur3.y); c[7] = make_float2(cur3.z, cur3.w);
        {
            const int off = (t + 1 < TSTEPS) ? (t + 1) * 128 : t * 128;
            cur0 = *(const float4*)(px + off);
            cur1 = *(const float4*)(px + off + 4);
            cur2 = *(const float4*)(px + off + 8);
            cur3 = *(const float4*)(px + off + 12);
        }

        // ---- phase 1: partial Hp = H_slice @ U1 ----
        float2 pa[RP / 2];
#pragma unroll
        for (int i = 0; i < RP / 2; i++) pa[i] = make_float2(0.f, 0.f);
#pragma unroll
        for (int jl = 0; jl < JT; jl++) {
            float hv = (jl & 1) ? H[jl >> 1].y : H[jl >> 1].x;
            float2 h2 = make_float2(hv, hv);
            const float4* urow = (const float4*)(U1s + (jl * GRP + g) * RP);
#pragma unroll
            for (int q = 0; q < 7; q++) {
                float4 u = urow[q];
                fma2(pa[2 * q],     h2, make_float2(u.x, u.y));
                fma2(pa[2 * q + 1], h2, make_float2(u.z, u.w));
            }
        }
        // ---- butterfly all-reduce over the 8 slice-lanes (r<26 matter) ----
#pragma unroll
        for (int i = 0; i < 13; i++) {
            float ax = pa[i].x, ay = pa[i].y;
            ax += __shfl_xor_sync(0xffffffffu, ax, 1);
            ay += __shfl_xor_sync(0xffffffffu, ay, 1);
            ax += __shfl_xor_sync(0xffffffffu, ax, 2);
            ay += __shfl_xor_sync(0xffffffffu, ay, 2);
            ax += __shfl_xor_sync(0xffffffffu, ax, 4);
            ay += __shfl_xor_sync(0xffffffffu, ay, 4);
            pa[i] = make_float2(ax, ay);
        }

        // ---- phase 2: c += Hp @ U2 (slice) ----
#pragma unroll
        for (int r = 0; r < RU; r++) {
            float hp = (r & 1) ? pa[r >> 1].y : pa[r >> 1].x;
            float2 h2 = make_float2(hp, hp);
            const float4* u = (const float4*)(U2s + r * U2ROW + g * SLST);
#pragma unroll
            for (int q = 0; q < 4; q++) {
                float4 uv = u[q];
                fma2(c[2 * q],     h2, make_float2(uv.x, uv.y));
                fma2(c[2 * q + 1], h2, make_float2(uv.z, uv.w));
            }
        }

        // ---- elementwise gate/update (sigmoid = 0.5*tanh(z/2)+0.5) ----
#pragma unroll
        for (int jl = 0; jl < JT; jl++) {
            float2 bb = bbv[jl];
            float cc = (jl & 1) ? c[jl >> 1].y : c[jl >> 1].x;
            float gg = fmaf(0.5f, tanha(0.5f * (cc + bb.x)), 0.5f);
            float hh = tanha(cc + bb.y);
            float ho = (jl & 1) ? H[jl >> 1].y : H[jl >> 1].x;
            float hn = fmaf(gg, ho - sz, fmaf(sn, hh, sz));
            if (jl & 1) H[jl >> 1].y = hn; else H[jl >> 1].x = hn;
        }
    }

    // ---- epilogue: score = H @ FC + FCbias ----
    float s[NCLS];
#pragma unroll
    for (int c = 0; c < NCLS; c++) s[c] = 0.f;
#pragma unroll
    for (int jl = 0; jl < JT; jl++) {
        int jg = g * JT + jl;
        if (jg < DH) {
            float hv = (jl & 1) ? H[jl >> 1].y : H[jl >> 1].x;
#pragma unroll
            for (int c = 0; c < NCLS; c++)
                s[c] = fmaf(hv, __ldg(FC + jg * NCLS + c), s[c]);
        }
    }
#pragma unroll
    for (int c = 0; c < NCLS; c++) {
        s[c] += __shfl_xor_sync(0xffffffffu, s[c], 1);
        s[c] += __shfl_xor_sync(0xffffffffu, s[c], 2);
        s[c] += __shfl_xor_sync(0xffffffffu, s[c], 4);
    }
    if (g == 0) {
#pragma unroll
        for (int c = 0; c < NCLS; c++)
            out[(size_t)row * NCLS + c] = s[c] + __ldg(FCb + c);
    }
}

// ---------------- launch ----------------
extern "C" void kernel_launch(void* const* d_in, const int* in_sizes, int n_in,
                              void* d_out, int out_size) {
    const float* x    = (const float*)d_in[0];
    const float* W1   = (const float*)d_in[1];
    const float* W2   = (const float*)d_in[2];
    const float* U1   = (const float*)d_in[3];
    const float* U2   = (const float*)d_in[4];
    const float* bg   = (const float*)d_in[5];
    const float* bu   = (const float*)d_in[6];
    const float* zeta = (const float*)d_in[7];
    const float* nu   = (const float*)d_in[8];
    const float* FC   = (const float*)d_in[9];
    const float* FCb  = (const float*)d_in[10];
    float* out = (float*)d_out;

    setup_kernel<<<32, 256>>>(W1, W2, U1, U2, bg, bu, zeta, nu);
    xw_kernel<<<XW_GRID, XW_THREADS>>>(x);
    grnn_kernel<<<NGRID, NTHREADS>>>(FC, FCb, out);
}

// round 10
// speedup vs baseline: 2.2176x; 2.2176x over previous
#include <cuda_runtime.h>
#include <cuda_bf16.h>
#include <mma.h>
#include <math.h>
#include <stdint.h>

using namespace nvcuda;

// ---------------- problem constants ----------------
#define BATCH   8192
#define TSTEPS  99
#define DIN     32
#define DH      100
#define RW      16
#define RU      25
#define NCLS    6
#define MROWS   64
#define NBLK    (BATCH / MROWS)      // 128
#define NTHR    256

// A: 64 x 296 bf16. cols: 0-111 Hhi, 112-223 Hlo, 224-255 xhi, 256-287 xlo
#define A_LD    296
#define A_BYTES (64 * A_LD * 2)          // 37888
// B: 288 x 136 bf16. rows: 0-111 Uhi, 112-223 Ulo, 224-255 Whi, 256-287 Wlo
#define B_LD    136
#define B_BYTES (288 * B_LD * 2)         // 78336
// C: 64 x 132 fp32
#define C_LD    132
#define C_BYTES (64 * C_LD * 4)          // 33792

#define SM_A    0
#define SM_B    (SM_A + A_BYTES)
#define SM_C    (SM_B + B_BYTES)
#define SM_BB   (SM_C + C_BYTES)
#define SM_TOT  (SM_BB + 1024)           // 151040 B

// ---------------- device-global prepped data ----------------
__device__ __align__(16) __nv_bfloat16 g_Bs[288 * B_LD];     // split/padded B image
__device__ float g_bb[224];                                   // (bg, bu) pairs, j-padded to 112
__device__ float g_sc[2];
__device__ __align__(16) __nv_bfloat16 g_AXB[(size_t)NBLK * TSTEPS * 4096]; // x hi/lo rows (104MB)

__device__ __forceinline__ float tanha(float v) {
    float r; asm("tanh.approx.f32 %0, %1;" : "=f"(r) : "f"(v)); return r;
}
__device__ __forceinline__ uint32_t pk2(__nv_bfloat16 a, __nv_bfloat16 b) {
    return (uint32_t)__bfloat16_as_ushort(a) | ((uint32_t)__bfloat16_as_ushort(b) << 16);
}

// ---------------- setup 1: weights -> split B image ----------------
__global__ void setup_w(const float* __restrict__ W1, const float* __restrict__ W2,
                        const float* __restrict__ U1, const float* __restrict__ U2,
                        const float* __restrict__ bg, const float* __restrict__ bu,
                        const float* __restrict__ zeta, const float* __restrict__ nu) {
    int tid = blockIdx.x * blockDim.x + threadIdx.x;
    int nth = gridDim.x * blockDim.x;
    for (int idx = tid; idx < 288 * B_LD; idx += nth) {
        int k = idx / B_LD, n = idx % B_LD;
        float v = 0.f;
        bool lo = false;
        if (n < DH) {
            if (k < 112) {                       // Uhi rows
                if (k < DH)
                    for (int r = 0; r < RU; r++) v = fmaf(U1[k * RU + r], U2[r * DH + n], v);
            } else if (k < 224) {                // Ulo rows
                int kk = k - 112; lo = true;
                if (kk < DH)
                    for (int r = 0; r < RU; r++) v = fmaf(U1[kk * RU + r], U2[r * DH + n], v);
            } else if (k < 256) {                // Whi rows
                int kk = k - 224;
                for (int r = 0; r < RW; r++) v = fmaf(W1[kk * RW + r], W2[r * DH + n], v);
            } else {                             // Wlo rows
                int kk = k - 256; lo = true;
                for (int r = 0; r < RW; r++) v = fmaf(W1[kk * RW + r], W2[r * DH + n], v);
            }
        }
        __nv_bfloat16 hi = __float2bfloat16_rn(v);
        g_Bs[idx] = lo ? __float2bfloat16_rn(v - __bfloat162float(hi)) : hi;
    }
    for (int j = tid; j < 112; j += nth) {
        g_bb[2 * j]     = (j < DH) ? bg[j] : 0.f;
        g_bb[2 * j + 1] = (j < DH) ? bu[j] : 0.f;
    }
    if (tid == 0) {
        g_sc[0] = 1.f / (1.f + expf(-zeta[0]));
        g_sc[1] = 1.f / (1.f + expf(-nu[0]));
    }
}

// ---------------- setup 2: x -> split hi/lo row images ----------------
__global__ void __launch_bounds__(256)
setup_x(const float* __restrict__ x) {
    int gid = blockIdx.x * 256 + threadIdx.x;          // (blk, t, r)
    int blk = gid / (TSTEPS * MROWS);
    int rem = gid % (TSTEPS * MROWS);
    int t = rem / MROWS, r = rem % MROWS;
    const float* xr = x + (size_t)(blk * MROWS + r) * (TSTEPS * DIN) + t * DIN;
    __nv_bfloat16 buf[64];
#pragma unroll
    for (int k = 0; k < DIN; k++) {
        float v = xr[k];
        __nv_bfloat16 hi = __float2bfloat16_rn(v);
        buf[k]      = hi;
        buf[32 + k] = __float2bfloat16_rn(v - __bfloat162float(hi));
    }
    uint4* dst = (uint4*)(g_AXB + ((size_t)(blk * TSTEPS + t)) * 4096 + r * 64);
    const uint4* src = (const uint4*)buf;
#pragma unroll
    for (int i = 0; i < 8; i++) dst[i] = src[i];
}

// ---------------- persistent WMMA recurrent kernel ----------------
__global__ void __launch_bounds__(NTHR)
grnn_kernel(const float* __restrict__ FC, const float* __restrict__ FCb,
            float* __restrict__ out) {
    extern __shared__ __align__(16) char sm[];
    __nv_bfloat16* As = (__nv_bfloat16*)(sm + SM_A);
    __nv_bfloat16* Bs = (__nv_bfloat16*)(sm + SM_B);
    float*  Cs  = (float*)(sm + SM_C);
    float2* bbs = (float2*)(sm + SM_BB);

    const int tid = threadIdx.x;
    const int blk = blockIdx.x;

    // ---- init: B copy, A zero, x(0), biases ----
    {
        uint4* d = (uint4*)Bs; const uint4* s = (const uint4*)g_Bs;
        for (int i = tid; i < B_BYTES / 16; i += NTHR) d[i] = s[i];
        d = (uint4*)As;
        for (int i = tid; i < A_BYTES / 16; i += NTHR) d[i] = make_uint4(0, 0, 0, 0);
        const uint4* xs0 = (const uint4*)(g_AXB + (size_t)blk * TSTEPS * 4096);
#pragma unroll
        for (int i2 = 0; i2 < 2; i2++) {
            int idx = tid + i2 * NTHR;                  // 0..511
            *(uint4*)((char*)As + (idx >> 3) * (A_LD * 2) + 448 + (idx & 7) * 16) = xs0[idx];
        }
        for (int j = tid; j < 112; j += NTHR)
            bbs[j] = make_float2(g_bb[2 * j], g_bb[2 * j + 1]);
    }
    __syncthreads();

    const float sz = g_sc[0];
    const float sn = g_sc[1];

    const int w = tid >> 5;
    const int p = w & 1;                 // m-pair: rows 32p..32p+31
    const int q = w >> 1;                // n-pair: cols 32q..32q+31

    const int erow  = tid >> 2;          // epilogue row 0..63
    const int ecq   = tid & 3;
    const int ecol0 = ecq * 28;          // epilogue cols ecol0..ecol0+27

    float H[28];
#pragma unroll
    for (int i = 0; i < 28; i++) H[i] = 0.f;

    wmma::fragment<wmma::accumulator, 16, 16, 16, float> cf[2][2];

    for (int t = 0; t < TSTEPS; t++) {
        // prefetch next step's x rows into registers
        uint4 xp0, xp1;
        const int hx = (t + 1 < TSTEPS);
        if (hx) {
            const uint4* s = (const uint4*)(g_AXB + (size_t)(blk * TSTEPS + t + 1) * 4096);
            xp0 = s[tid]; xp1 = s[tid + NTHR];
        }

        // ---- MMA phase ----
#pragma unroll
        for (int mi = 0; mi < 2; mi++)
#pragma unroll
            for (int ni = 0; ni < 2; ni++) wmma::fill_fragment(cf[mi][ni], 0.f);

        wmma::fragment<wmma::matrix_a, 16, 16, 16, __nv_bfloat16, wmma::row_major> ah[2], al[2];
        wmma::fragment<wmma::matrix_b, 16, 16, 16, __nv_bfloat16, wmma::row_major> bh[2], bl[2];

        // U part: K-steps over H (cols 0..111 hi, 112..223 lo; B rows likewise)
#pragma unroll
        for (int kk = 0; kk < 7; kk++) {
#pragma unroll
            for (int mi = 0; mi < 2; mi++) {
                const __nv_bfloat16* ar = As + (32 * p + 16 * mi) * A_LD + 16 * kk;
                wmma::load_matrix_sync(ah[mi], ar, A_LD);
                wmma::load_matrix_sync(al[mi], ar + 112, A_LD);
            }
#pragma unroll
            for (int ni = 0; ni < 2; ni++) {
                const __nv_bfloat16* br = Bs + (16 * kk) * B_LD + 32 * q + 16 * ni;
                wmma::load_matrix_sync(bh[ni], br, B_LD);
                wmma::load_matrix_sync(bl[ni], br + 112 * B_LD, B_LD);
            }
#pragma unroll
            for (int mi = 0; mi < 2; mi++)
#pragma unroll
                for (int ni = 0; ni < 2; ni++) {
                    wmma::mma_sync(cf[mi][ni], ah[mi], bh[ni], cf[mi][ni]);
                    wmma::mma_sync(cf[mi][ni], al[mi], bh[ni], cf[mi][ni]);
                    wmma::mma_sync(cf[mi][ni], ah[mi], bl[ni], cf[mi][ni]);
                }
        }
        // x part: cols 224..255 hi, 256..287 lo; B rows 224..255 Whi, 256..287 Wlo
#pragma unroll
        for (int kk = 0; kk < 2; kk++) {
#pragma unroll
            for (int mi = 0; mi < 2; mi++) {
                const __nv_bfloat16* ar = As + (32 * p + 16 * mi) * A_LD + 224 + 16 * kk;
                wmma::load_matrix_sync(ah[mi], ar, A_LD);
                wmma::load_matrix_sync(al[mi], ar + 32, A_LD);
            }
#pragma unroll
            for (int ni = 0; ni < 2; ni++) {
                const __nv_bfloat16* br = Bs + (224 + 16 * kk) * B_LD + 32 * q + 16 * ni;
                wmma::load_matrix_sync(bh[ni], br, B_LD);
                wmma::load_matrix_sync(bl[ni], br + 32 * B_LD, B_LD);
            }
#pragma unroll
            for (int mi = 0; mi < 2; mi++)
#pragma unroll
                for (int ni = 0; ni < 2; ni++) {
                    wmma::mma_sync(cf[mi][ni], ah[mi], bh[ni], cf[mi][ni]);
                    wmma::mma_sync(cf[mi][ni], al[mi], bh[ni], cf[mi][ni]);
                    wmma::mma_sync(cf[mi][ni], ah[mi], bl[ni], cf[mi][ni]);
                }
        }
        // store c to smem
#pragma unroll
        for (int mi = 0; mi < 2; mi++)
#pragma unroll
            for (int ni = 0; ni < 2; ni++)
                wmma::store_matrix_sync(Cs + (32 * p + 16 * mi) * C_LD + 32 * q + 16 * ni,
                                        cf[mi][ni], C_LD, wmma::mem_row_major);
        __syncthreads();

        // ---- epilogue: gates + H update + write-back ----
        const float* crow = Cs + erow * C_LD + ecol0;
        float cc[28];
#pragma unroll
        for (int i4 = 0; i4 < 7; i4++) {
            float4 v = *(const float4*)(crow + 4 * i4);
            cc[4 * i4] = v.x; cc[4 * i4 + 1] = v.y; cc[4 * i4 + 2] = v.z; cc[4 * i4 + 3] = v.w;
        }
#pragma unroll
        for (int i = 0; i < 28; i++) {
            float2 bb = bbs[ecol0 + i];
            float gg = fmaf(0.5f, tanha(0.5f * (cc[i] + bb.x)), 0.5f);
            float hh = tanha(cc[i] + bb.y);
            H[i] = fmaf(gg, H[i] - sz, fmaf(sn, hh, sz));
        }
        char* arow = (char*)As + erow * (A_LD * 2);
#pragma unroll
        for (int i2 = 0; i2 < 14; i2++) {
            float h0 = H[2 * i2], h1 = H[2 * i2 + 1];
            __nv_bfloat16 h0h = __float2bfloat16_rn(h0);
            __nv_bfloat16 h1h = __float2bfloat16_rn(h1);
            __nv_bfloat16 h0l = __float2bfloat16_rn(h0 - __bfloat162float(h0h));
            __nv_bfloat16 h1l = __float2bfloat16_rn(h1 - __bfloat162float(h1h));
            *(uint32_t*)(arow + (ecol0 + 2 * i2) * 2)         = pk2(h0h, h1h);
            *(uint32_t*)(arow + (112 + ecol0 + 2 * i2) * 2)   = pk2(h0l, h1l);
        }
        if (hx) {
            *(uint4*)((char*)As + (tid >> 3) * (A_LD * 2) + 448 + (tid & 7) * 16)        = xp0;
            *(uint4*)((char*)As + ((tid >> 3) + 32) * (A_LD * 2) + 448 + (tid & 7) * 16) = xp1;
        }
        __syncthreads();
    }

    // ---- scores: per-thread partial over 28 cols, reduce across the 4 quarter-threads ----
    float s[NCLS];
#pragma unroll
    for (int c = 0; c < NCLS; c++) s[c] = 0.f;
#pragma unroll
    for (int i = 0; i < 28; i++) {
        int j = ecol0 + i;
        if (j < DH) {
            float hv = H[i];
#pragma unroll
            for (int c = 0; c < NCLS; c++)
                s[c] = fmaf(hv, __ldg(FC + j * NCLS + c), s[c]);
        }
    }
#pragma unroll
    for (int c = 0; c < NCLS; c++) {
        s[c] += __shfl_xor_sync(0xffffffffu, s[c], 1);
        s[c] += __shfl_xor_sync(0xffffffffu, s[c], 2);
    }
    if (ecq == 0) {
        int grow = blk * MROWS + erow;
#pragma unroll
        for (int c = 0; c < NCLS; c++)
            out[(size_t)grow * NCLS + c] = s[c] + __ldg(FCb + c);
    }
}

// ---------------- launch ----------------
extern "C" void kernel_launch(void* const* d_in, const int* in_sizes, int n_in,
                              void* d_out, int out_size) {
    const float* x    = (const float*)d_in[0];
    const float* W1   = (const float*)d_in[1];
    const float* W2   = (const float*)d_in[2];
    const float* U1   = (const float*)d_in[3];
    const float* U2   = (const float*)d_in[4];
    const float* bg   = (const float*)d_in[5];
    const float* bu   = (const float*)d_in[6];
    const float* zeta = (const float*)d_in[7];
    const float* nu   = (const float*)d_in[8];
    const float* FC   = (const float*)d_in[9];
    const float* FCb  = (const float*)d_in[10];
    float* out = (float*)d_out;

    cudaFuncSetAttribute(grnn_kernel, cudaFuncAttributeMaxDynamicSharedMemorySize, SM_TOT);

    setup_w<<<16, 256>>>(W1, W2, U1, U2, bg, bu, zeta, nu);
    setup_x<<<(NBLK * TSTEPS * MROWS) / 256, 256>>>(x);
    grnn_kernel<<<NBLK, NTHR, SM_TOT>>>(FC, FCb, out);
}